// round 5
// baseline (speedup 1.0000x reference)
#include <cuda_runtime.h>
#include <math.h>
#include <float.h>

#define BN 8
#define H 480
#define W 640
#define OH 120
#define OW 160
#define CH 128
#define NP 192

typedef unsigned long long u64;

// ---------------- scratch ----------------
__device__ float d_cellval[BN*256];
__device__ int   d_cellxy[BN*256];
__device__ int   d_selxy[BN*NP];
// channel-last fmap copy: [b][oy][ox][ch]  (8*120*160*128 floats = 78.6MB)
__device__ float d_cl[(size_t)BN*OH*OW*CH];

// ---------------- f32x2 helpers ----------------
__device__ __forceinline__ u64 pack2(float lo, float hi) {
    u64 r; asm("mov.b64 %0, {%1, %2};" : "=l"(r) : "f"(lo), "f"(hi)); return r;
}
__device__ __forceinline__ void unpack2(u64 v, float& lo, float& hi) {
    asm("mov.b64 {%0, %1}, %2;" : "=f"(lo), "=f"(hi) : "l"(v));
}
__device__ __forceinline__ u64 ffma2(u64 a, u64 b, u64 c) {
    u64 d; asm("fma.rn.f32x2 %0, %1, %2, %3;" : "=l"(d) : "l"(a), "l"(b), "l"(c)); return d;
}

// ================= K1: fused harris + per-cell argmax =================
__global__ __launch_bounds__(256) void k_harris(const float* __restrict__ frame) {
    __shared__ float sf[37][48];
    __shared__ float spxx[36][48], spyy[36][48], spxy[36][48];
    __shared__ float shxx[36][40], shyy[36][40], shxy[36][40];
    __shared__ float sv[256];
    __shared__ int   si[256];

    int blk = blockIdx.x;
    int b = blk >> 8, cell = blk & 255;
    int gh = cell >> 4, gw = cell & 15;
    int gx0 = gw * 40, gy0 = gh * 30;
    int X0 = gx0 - 3, Y0 = gy0 - 3;
    const float* f = frame + (size_t)b * H * W;
    int tid = threadIdx.x;

    for (int i = tid; i < 37 * 47; i += 256) {
        int r = i / 47, c = i - r * 47;
        int x = X0 + c, y = Y0 + r;
        sf[r][c] = (x >= 0 && x < W && y >= 0 && y < H) ? f[y * W + x] : 0.f;
    }
    __syncthreads();

    for (int i = tid; i < 36 * 46; i += 256) {
        int r = i / 46, c = i - r * 46;
        int x = X0 + c, y = Y0 + r;
        float pxx = 0.f, pyy = 0.f, pxy = 0.f;
        if (x >= 0 && x < W && y >= 0 && y < H) {
            float dx = (x < W - 1) ? (sf[r][c+1] - sf[r][c]) : (sf[r][c-1] - sf[r][c-2]);
            float dy = (y < H - 1) ? (sf[r+1][c] - sf[r][c]) : (sf[r-1][c] - sf[r-2][c]);
            pxx = dx * dx; pyy = dy * dy; pxy = dx * dy;
        }
        spxx[r][c] = pxx; spyy[r][c] = pyy; spxy[r][c] = pxy;
    }
    __syncthreads();

    for (int i = tid; i < 36 * 40; i += 256) {
        int r = i / 40, c = i - r * 40;
        float a = 0.f, bb = 0.f, cc = 0.f;
        #pragma unroll
        for (int k = 0; k < 7; k++) {
            a  += spxx[r][c + k];
            bb += spyy[r][c + k];
            cc += spxy[r][c + k];
        }
        shxx[r][c] = a; shyy[r][c] = bb; shxy[r][c] = cc;
    }
    __syncthreads();

    float bv = -FLT_MAX;
    int   bi = 0x7FFFFFFF;
    for (int fi = tid; fi < 1200; fi += 256) {
        int py = fi / 40, px = fi - py * 40;
        float a = 0.f, bb = 0.f, cc = 0.f;
        #pragma unroll
        for (int k = 0; k < 7; k++) {
            a  += shxx[py + k][px];
            bb += shyy[py + k][px];
            cc += shxy[py + k][px];
        }
        float Ixx = a / 49.0f, Iyy = bb / 49.0f, Ixy = cc / 49.0f;
        float g = (Ixx * Iyy - Ixy * Ixy) / (Ixx + Iyy + 1e-8f);
        if (g > bv) { bv = g; bi = fi; }
    }
    sv[tid] = bv; si[tid] = bi;
    __syncthreads();
    for (int s = 128; s > 0; s >>= 1) {
        if (tid < s) {
            float v2 = sv[tid + s]; int i2 = si[tid + s];
            if (v2 > sv[tid] || (v2 == sv[tid] && i2 < si[tid])) { sv[tid] = v2; si[tid] = i2; }
        }
        __syncthreads();
    }
    if (tid == 0) {
        int fi = si[0];
        int py = fi / 40, px = fi - py * 40;
        d_cellval[blk] = sv[0];
        d_cellxy[blk]  = ((gy0 + py) << 16) | (gx0 + px);
    }
}

// ================= K2: top-192 by rank count (stable) =================
__global__ void k_topk(float* __restrict__ out_coords) {
    __shared__ float sv[256];
    __shared__ int   sxy[256];
    int b = blockIdx.x, i = threadIdx.x;
    sv[i]  = d_cellval[b*256 + i];
    sxy[i] = d_cellxy[b*256 + i];
    __syncthreads();
    float v = sv[i];
    int rank = 0;
    #pragma unroll 8
    for (int j = 0; j < 256; j++) {
        float vj = sv[j];
        rank += (vj > v) || (vj == v && j < i);
    }
    if (rank < NP) {
        int xy = sxy[i];
        int x = xy & 0xFFFF, y = xy >> 16;
        out_coords[((size_t)b*NP + rank)*2 + 0] = (float)x;
        out_coords[((size_t)b*NP + rank)*2 + 1] = (float)y;
        d_selxy[b*NP + rank] = xy;
    }
}

// ================= K3: conv v5 =================
// Block: 128 thr = 4 warps. warp bit1 = oy row (oyr), bit0 = channel half.
// Thread: channel pair cp = chh*32+lane, 16 px, one oy row.
// Weights in smem (paired u64, stride-65 conflict-free). Inputs in smem as
// duplicated (v,v) pairs, fetched via LDS.128 bursts. Dual store: required
// layout via smem-staged coalesced STG + channel-last d_cl direct coalesced.
#define W_STRIDE 65
#define W_WORDS  3186              // 49*65 = 3185, pad to even for 16B align
#define IN_STRIDE 72
#define IN_WORDS (11*IN_STRIDE)    // 792

__global__ __launch_bounds__(128, 4) void k_conv(
    const float* __restrict__ frame,
    const float* __restrict__ wf,
    const float* __restrict__ bf,
    float* __restrict__ fmap)
{
    __shared__ __align__(16) u64 s_w[W_WORDS];     // [tap][cp] stride 65; later overlaid by sout
    __shared__ __align__(16) u64 s_in[IN_WORDS];   // [row][col] duplicated pairs
    float* s_out = (float*)s_w;                    // overlay: [oyr][ch][16] = 16KB

    int tid  = threadIdx.x;
    int lane = tid & 31;
    int warp = tid >> 5;
    int oyr  = warp >> 1;
    int chh  = warp & 1;
    int cp   = chh * 32 + lane;
    int c0   = cp * 2;

    int ox0 = blockIdx.x * 16;
    int oy0 = blockIdx.y * 2;
    int b   = blockIdx.z;
    const float* f = frame + (size_t)b * H * W;
    int row0 = oy0 * 4 - 3, col0 = ox0 * 4 - 3;

    // load weights into smem, paired by channel
    for (int i = tid; i < 64 * 49; i += 128) {
        int wcp = i / 49, t = i - wcp * 49;
        s_w[t * W_STRIDE + wcp] = pack2(__ldg(wf + (wcp*2)*49 + t),
                                        __ldg(wf + (wcp*2+1)*49 + t));
    }
    // load input window (duplicated pairs), 11 rows x 67 cols
    for (int i = tid; i < 11 * 67; i += 128) {
        int r = i / 67, c = i - r * 67;
        int y = row0 + r, x = col0 + c;
        float v = (y >= 0 && y < H && x >= 0 && x < W) ? f[(size_t)y*W + x] : 0.f;
        s_in[r * IN_STRIDE + c] = pack2(v, v);
    }
    u64 bias2 = pack2(__ldg(bf + c0), __ldg(bf + c0 + 1));
    __syncthreads();

    u64 acc[16];
    #pragma unroll
    for (int i = 0; i < 16; i++) acc[i] = bias2;

    #pragma unroll
    for (int ky = 0; ky < 7; ky++) {
        int row = oyr * 4 + ky;
        u64 wk[7];
        #pragma unroll
        for (int kx = 0; kx < 7; kx++) wk[kx] = s_w[(ky*7 + kx) * W_STRIDE + cp];
        #pragma unroll
        for (int g = 0; g < 4; g++) {
            const ulonglong2* p = (const ulonglong2*)(s_in + row * IN_STRIDE + g * 16);
            u64 in[20];
            #pragma unroll
            for (int k = 0; k < 10; k++) { ulonglong2 t2 = p[k]; in[2*k] = t2.x; in[2*k+1] = t2.y; }
            #pragma unroll
            for (int j = 0; j < 4; j++) {
                #pragma unroll
                for (int kx = 0; kx < 7; kx++)
                    acc[g*4 + j] = ffma2(in[j*4 + kx], wk[kx], acc[g*4 + j]);
            }
        }
    }

    // relu + channel-last store (coalesced 256B per warp per px)
    int oy = oy0 + oyr;
    float lo[16], hi[16];
    #pragma unroll
    for (int px = 0; px < 16; px++) {
        float a0, a1; unpack2(acc[px], a0, a1);
        lo[px] = fmaxf(a0, 0.f); hi[px] = fmaxf(a1, 0.f);
        u64* clp = (u64*)(d_cl + (((size_t)(b*OH + oy))*OW + ox0 + px) * CH + c0);
        *clp = pack2(lo[px], hi[px]);
    }

    // stage required layout into smem (weights dead now)
    __syncthreads();
    #pragma unroll
    for (int px = 0; px < 16; px++) {
        s_out[(oyr*128 + c0  ) * 16 + px] = lo[px];
        s_out[(oyr*128 + c0+1) * 16 + px] = hi[px];
    }
    __syncthreads();

    // coalesced copy-out
    for (int i = tid; i < 2 * 128 * 16; i += 128) {
        int px = i & 15;
        int ch = (i >> 4) & 127;
        int r  = i >> 11;
        fmap[(((size_t)(b*CH + ch)) * OH + (oy0 + r)) * OW + ox0 + px] = s_out[(r*128 + ch)*16 + px];
    }
}

// ================= K4: patches_f v4 — channel-last coalesced gather =============
// Block per keypoint, 128 threads = 128 channels. 64 window points, each a
// 512B coalesced load. Bilinear in registers, smem-staged coalesced output.
__global__ __launch_bounds__(128) void k_patches_f(float* __restrict__ out) {
    __shared__ float s[CH * 49];
    int bp = blockIdx.x;
    int b  = bp / NP;
    int c  = threadIdx.x;
    int xy = d_selxy[bp];
    float fx = (float)(xy & 0xFFFF) * 0.25f;
    float fy = (float)(xy >> 16)    * 0.25f;
    int x0 = (int)floorf(fx);
    int y0 = (int)floorf(fy);
    float wx = fx - (float)x0, wy = fy - (float)y0;
    int gx0 = x0 - 3, gy0 = y0 - 3;

    const float* base = d_cl + (size_t)b * OH * OW * CH + c;

    float v[64];
    #pragma unroll
    for (int pt = 0; pt < 64; pt++) {
        int yy = pt >> 3, xx = pt & 7;
        int gy = gy0 + yy, gx = gx0 + xx;
        bool ok = (gx >= 0) & (gx < OW) & (gy >= 0) & (gy < OH);
        v[pt] = ok ? __ldg(base + ((size_t)gy * OW + gx) * CH) : 0.f;
    }

    float w00 = (1.f - wx) * (1.f - wy);
    float w10 = wx * (1.f - wy);
    float w01 = (1.f - wx) * wy;
    float w11 = wx * wy;

    #pragma unroll
    for (int j = 0; j < 7; j++) {
        #pragma unroll
        for (int i = 0; i < 7; i++) {
            float acc = v[j*8 + i]       * w00
                      + v[j*8 + i + 1]   * w10
                      + v[(j+1)*8 + i]   * w01
                      + v[(j+1)*8 + i+1] * w11;
            s[c * 49 + (j*7 + i)] = acc;
        }
    }
    __syncthreads();

    float* o = out + (size_t)bp * (CH * 49);
    for (int k = threadIdx.x; k < CH * 49; k += 128)
        o[k] = s[k];
}

// ================= K5: patches_c — on-the-fly imap conv =================
__global__ void k_patches_c(
    const float* __restrict__ frame,
    const float* __restrict__ wc,
    const float* __restrict__ bc,
    float* __restrict__ out)
{
    __shared__ float s_in[121];
    int bp = blockIdx.x;
    int b  = bp / NP;
    int c  = threadIdx.x;
    int xy = d_selxy[bp];
    float fx = (float)(xy & 0xFFFF) * 0.25f;
    float fy = (float)(xy >> 16)    * 0.25f;
    int x0 = (int)floorf(fx);
    int y0 = (int)floorf(fy);
    float wx = fx - (float)x0, wy = fy - (float)y0;

    const float* f = frame + (size_t)b * H * W;
    int row0 = y0 * 4 - 3, col0 = x0 * 4 - 3;
    for (int i = threadIdx.x; i < 121; i += 128) {
        int r = i / 11, cc = i - r * 11;
        int yyy = row0 + r, xxx = col0 + cc;
        s_in[i] = (yyy >= 0 && yyy < H && xxx >= 0 && xxx < W) ? f[yyy*W + xxx] : 0.f;
    }
    float wreg[49];
    #pragma unroll
    for (int i = 0; i < 49; i++) wreg[i] = __ldg(wc + c*49 + i);
    float bias = __ldg(bc + c);
    __syncthreads();

    float wts[4] = { (1.f-wx)*(1.f-wy), wx*(1.f-wy), (1.f-wx)*wy, wx*wy };
    float acc = 0.f;
    #pragma unroll
    for (int n = 0; n < 4; n++) {
        int dxn = n & 1, dyn = n >> 1;
        int xi = x0 + dxn, yi = y0 + dyn;
        if (xi < OW && yi < OH) {
            float v = bias;
            #pragma unroll
            for (int ky = 0; ky < 7; ky++)
                #pragma unroll
                for (int kx = 0; kx < 7; kx++)
                    v = fmaf(s_in[(dyn*4 + ky)*11 + (dxn*4 + kx)], wreg[ky*7 + kx], v);
            v = fmaxf(v, 0.f);
            acc += v * wts[n];
        }
    }
    out[(size_t)bp * CH + c] = acc;
}

// ---------------- launch: fork-join across two streams ---------------------------
extern "C" void kernel_launch(void* const* d_in, const int* in_sizes, int n_in,
                              void* d_out, int out_size) {
    const float* frame = (const float*)d_in[0];
    const float* w_f   = (const float*)d_in[1];
    const float* b_f   = (const float*)d_in[2];
    const float* w_c   = (const float*)d_in[3];
    const float* b_c   = (const float*)d_in[4];

    float* out        = (float*)d_out;
    float* out_coords = out;                                   // 8*192*2
    float* out_pf     = out + 3072;                            // 8*192*128*49
    float* out_pc     = out + 3072 + 9633792;                  // 8*192*128
    float* out_fmap   = out + 3072 + 9633792 + 196608;         // 8*128*120*160

    static cudaStream_t s1 = 0;
    static cudaEvent_t e_fork = 0, e_topk = 0, e_side = 0;
    if (!s1) {
        cudaStreamCreateWithFlags(&s1, cudaStreamNonBlocking);
        cudaEventCreateWithFlags(&e_fork, cudaEventDisableTiming);
        cudaEventCreateWithFlags(&e_topk, cudaEventDisableTiming);
        cudaEventCreateWithFlags(&e_side, cudaEventDisableTiming);
    }

    // fork
    cudaEventRecord(e_fork, 0);
    cudaStreamWaitEvent(s1, e_fork, 0);

    // side stream: harris -> topk -> patches_c
    k_harris<<<BN*256, 256, 0, s1>>>(frame);
    k_topk  <<<BN, 256, 0, s1>>>(out_coords);
    cudaEventRecord(e_topk, s1);
    k_patches_c<<<BN*NP, 128, 0, s1>>>(frame, w_c, b_c, out_pc);
    cudaEventRecord(e_side, s1);

    // main stream: conv, then patches_f (needs conv output AND topk coords)
    dim3 gconv(OW/16, OH/2, BN);
    k_conv<<<gconv, 128>>>(frame, w_f, b_f, out_fmap);
    cudaStreamWaitEvent(0, e_topk, 0);
    k_patches_f<<<BN*NP, 128>>>(out_pf);

    // join
    cudaStreamWaitEvent(0, e_side, 0);
}

// round 6
// speedup vs baseline: 1.1448x; 1.1448x over previous
#include <cuda_runtime.h>
#include <math.h>
#include <float.h>

#define BN 8
#define H 480
#define W 640
#define OH 120
#define OW 160
#define CH 128
#define NP 192

typedef unsigned long long u64;

// ---------------- scratch ----------------
__device__ float d_cellval[BN*256];
__device__ int   d_cellxy[BN*256];
__device__ int   d_selxy[BN*NP];
// channel-last fmap copy: [b][oy][ox][ch]
__device__ float d_cl[(size_t)BN*OH*OW*CH];
// pre-paired weights/bias for conv: [tap][pair] and [pair]
__device__ u64 d_wpair[49*64];
__device__ u64 d_bpair[64];

// ---------------- f32x2 helpers ----------------
__device__ __forceinline__ u64 pack2(float lo, float hi) {
    u64 r; asm("mov.b64 %0, {%1, %2};" : "=l"(r) : "f"(lo), "f"(hi)); return r;
}
__device__ __forceinline__ void unpack2(u64 v, float& lo, float& hi) {
    asm("mov.b64 {%0, %1}, %2;" : "=f"(lo), "=f"(hi) : "l"(v));
}
__device__ __forceinline__ u64 ffma2(u64 a, u64 b, u64 c) {
    u64 d; asm("fma.rn.f32x2 %0, %1, %2, %3;" : "=l"(d) : "l"(a), "l"(b), "l"(c)); return d;
}

// ================= K0: weight prep (one-time transpose into pairs) =============
__global__ void k_wprep(const float* __restrict__ wf, const float* __restrict__ bf) {
    int i = blockIdx.x * blockDim.x + threadIdx.x;
    if (i < 49*64) {
        int t = i >> 6, p = i & 63;
        d_wpair[i] = pack2(__ldg(wf + (2*p)*49 + t), __ldg(wf + (2*p+1)*49 + t));
    }
    if (i < 64) d_bpair[i] = pack2(__ldg(bf + 2*i), __ldg(bf + 2*i + 1));
}

// ================= K1: fused harris + per-cell argmax =================
__global__ __launch_bounds__(256) void k_harris(const float* __restrict__ frame) {
    __shared__ float sf[37][48];
    __shared__ float spxx[36][48], spyy[36][48], spxy[36][48];
    __shared__ float shxx[36][40], shyy[36][40], shxy[36][40];
    __shared__ float sv[256];
    __shared__ int   si[256];

    int blk = blockIdx.x;
    int b = blk >> 8, cell = blk & 255;
    int gh = cell >> 4, gw = cell & 15;
    int gx0 = gw * 40, gy0 = gh * 30;
    int X0 = gx0 - 3, Y0 = gy0 - 3;
    const float* f = frame + (size_t)b * H * W;
    int tid = threadIdx.x;

    for (int i = tid; i < 37 * 47; i += 256) {
        int r = i / 47, c = i - r * 47;
        int x = X0 + c, y = Y0 + r;
        sf[r][c] = (x >= 0 && x < W && y >= 0 && y < H) ? f[y * W + x] : 0.f;
    }
    __syncthreads();

    for (int i = tid; i < 36 * 46; i += 256) {
        int r = i / 46, c = i - r * 46;
        int x = X0 + c, y = Y0 + r;
        float pxx = 0.f, pyy = 0.f, pxy = 0.f;
        if (x >= 0 && x < W && y >= 0 && y < H) {
            float dx = (x < W - 1) ? (sf[r][c+1] - sf[r][c]) : (sf[r][c-1] - sf[r][c-2]);
            float dy = (y < H - 1) ? (sf[r+1][c] - sf[r][c]) : (sf[r-1][c] - sf[r-2][c]);
            pxx = dx * dx; pyy = dy * dy; pxy = dx * dy;
        }
        spxx[r][c] = pxx; spyy[r][c] = pyy; spxy[r][c] = pxy;
    }
    __syncthreads();

    for (int i = tid; i < 36 * 40; i += 256) {
        int r = i / 40, c = i - r * 40;
        float a = 0.f, bb = 0.f, cc = 0.f;
        #pragma unroll
        for (int k = 0; k < 7; k++) {
            a  += spxx[r][c + k];
            bb += spyy[r][c + k];
            cc += spxy[r][c + k];
        }
        shxx[r][c] = a; shyy[r][c] = bb; shxy[r][c] = cc;
    }
    __syncthreads();

    float bv = -FLT_MAX;
    int   bi = 0x7FFFFFFF;
    for (int fi = tid; fi < 1200; fi += 256) {
        int py = fi / 40, px = fi - py * 40;
        float a = 0.f, bb = 0.f, cc = 0.f;
        #pragma unroll
        for (int k = 0; k < 7; k++) {
            a  += shxx[py + k][px];
            bb += shyy[py + k][px];
            cc += shxy[py + k][px];
        }
        float Ixx = a / 49.0f, Iyy = bb / 49.0f, Ixy = cc / 49.0f;
        float g = (Ixx * Iyy - Ixy * Ixy) / (Ixx + Iyy + 1e-8f);
        if (g > bv) { bv = g; bi = fi; }
    }
    sv[tid] = bv; si[tid] = bi;
    __syncthreads();
    for (int s = 128; s > 0; s >>= 1) {
        if (tid < s) {
            float v2 = sv[tid + s]; int i2 = si[tid + s];
            if (v2 > sv[tid] || (v2 == sv[tid] && i2 < si[tid])) { sv[tid] = v2; si[tid] = i2; }
        }
        __syncthreads();
    }
    if (tid == 0) {
        int fi = si[0];
        int py = fi / 40, px = fi - py * 40;
        d_cellval[blk] = sv[0];
        d_cellxy[blk]  = ((gy0 + py) << 16) | (gx0 + px);
    }
}

// ================= K2: top-192 by rank count (stable) =================
__global__ void k_topk(float* __restrict__ out_coords) {
    __shared__ float sv[256];
    __shared__ int   sxy[256];
    int b = blockIdx.x, i = threadIdx.x;
    sv[i]  = d_cellval[b*256 + i];
    sxy[i] = d_cellxy[b*256 + i];
    __syncthreads();
    float v = sv[i];
    int rank = 0;
    #pragma unroll 8
    for (int j = 0; j < 256; j++) {
        float vj = sv[j];
        rank += (vj > v) || (vj == v && j < i);
    }
    if (rank < NP) {
        int xy = sxy[i];
        int x = xy & 0xFFFF, y = xy >> 16;
        out_coords[((size_t)b*NP + rank)*2 + 0] = (float)x;
        out_coords[((size_t)b*NP + rank)*2 + 1] = (float)y;
        d_selxy[b*NP + rank] = xy;
    }
}

// ================= K3: conv v6 =================
// Block 128 thr = 4 warps; warp -> (oyr = w>>1, pxh = w&1). Lane owns 2 channel
// pairs (cA=2*lane, cB=64+2*lane) x 8 px of one output row. Weights from
// d_wpair via coalesced copy; inputs duplicated (v,v) in smem, broadcast LDS.
__global__ __launch_bounds__(128, 6) void k_conv(
    const float* __restrict__ frame,
    float* __restrict__ fmap)
{
    __shared__ __align__(16) u64 s_w[49*64];    // 25088 B; overlaid by sout later
    __shared__ __align__(16) u64 s_in[11*68];   // 5984 B
    float* s_out = (float*)s_w;                 // overlay: [oyr][ch][16] = 16 KB

    int tid  = threadIdx.x;
    int lane = tid & 31;
    int warp = tid >> 5;
    int oyr  = warp >> 1;
    int pxh  = warp & 1;

    int ox0 = blockIdx.x * 16;
    int oy0 = blockIdx.y * 2;
    int b   = blockIdx.z;
    const float* f = frame + (size_t)b * H * W;
    int row0 = oy0 * 4 - 3, col0 = ox0 * 4 - 3;

    // coalesced weight copy (LDG.64, consecutive)
    for (int i = tid; i < 49*64; i += 128) s_w[i] = d_wpair[i];
    // input window: 11 rows x 67 cols, duplicated pairs
    for (int i = tid; i < 11*67; i += 128) {
        int r = i / 67, c = i - r * 67;
        int y = row0 + r, x = col0 + c;
        float v = (y >= 0 && y < H && x >= 0 && x < W) ? f[(size_t)y*W + x] : 0.f;
        s_in[r * 68 + c] = pack2(v, v);
    }
    u64 biasA = d_bpair[lane];
    u64 biasB = d_bpair[32 + lane];
    __syncthreads();

    u64 accA[8], accB[8];
    #pragma unroll
    for (int i = 0; i < 8; i++) { accA[i] = biasA; accB[i] = biasB; }

    #pragma unroll
    for (int ky = 0; ky < 7; ky++) {
        int row = oyr * 4 + ky;
        u64 wkA[7], wkB[7];
        #pragma unroll
        for (int kx = 0; kx < 7; kx++) {
            wkA[kx] = s_w[(ky*7 + kx) * 64 + lane];
            wkB[kx] = s_w[(ky*7 + kx) * 64 + 32 + lane];
        }
        const u64* inp = s_in + row * 68 + pxh * 32;
        #pragma unroll
        for (int c = 0; c < 35; c++) {
            u64 v = inp[c];
            if (c < 32) {
                int px = c >> 2, kx = c & 3;
                accA[px] = ffma2(v, wkA[kx], accA[px]);
                accB[px] = ffma2(v, wkB[kx], accB[px]);
            }
            if (c >= 4 && (c & 3) < 3) {
                int px = (c - 4) >> 2, kx = 4 + (c & 3);
                accA[px] = ffma2(v, wkA[kx], accA[px]);
                accB[px] = ffma2(v, wkB[kx], accB[px]);
            }
        }
    }

    // relu + channel-last store (coalesced 256B segments per warp per px)
    int oy = oy0 + oyr;
    int cA = 2 * lane, cB = 64 + 2 * lane;
    float loA[8], hiA[8], loB[8], hiB[8];
    #pragma unroll
    for (int px = 0; px < 8; px++) {
        float a0, a1;
        unpack2(accA[px], a0, a1); loA[px] = fmaxf(a0, 0.f); hiA[px] = fmaxf(a1, 0.f);
        unpack2(accB[px], a0, a1); loB[px] = fmaxf(a0, 0.f); hiB[px] = fmaxf(a1, 0.f);
        int ox = ox0 + pxh * 8 + px;
        u64* clp = (u64*)(d_cl + (((size_t)(b*OH + oy))*OW + ox) * CH);
        clp[lane]      = pack2(loA[px], hiA[px]);
        clp[32 + lane] = pack2(loB[px], hiB[px]);
    }

    // stage required layout into smem (weights dead now)
    __syncthreads();
    #pragma unroll
    for (int px = 0; px < 8; px++) {
        int pxg = pxh * 8 + px;
        s_out[(oyr*128 + cA  ) * 16 + pxg] = loA[px];
        s_out[(oyr*128 + cA+1) * 16 + pxg] = hiA[px];
        s_out[(oyr*128 + cB  ) * 16 + pxg] = loB[px];
        s_out[(oyr*128 + cB+1) * 16 + pxg] = hiB[px];
    }
    __syncthreads();

    for (int i = tid; i < 2 * 128 * 16; i += 128) {
        int px = i & 15;
        int ch = (i >> 4) & 127;
        int r  = i >> 11;
        fmap[(((size_t)(b*CH + ch)) * OH + (oy0 + r)) * OW + ox0 + px] = s_out[(r*128 + ch)*16 + px];
    }
}

// ================= K4: patches_f — channel-last coalesced gather =============
__global__ __launch_bounds__(128) void k_patches_f(float* __restrict__ out) {
    __shared__ float s[CH * 49];
    int bp = blockIdx.x;
    int b  = bp / NP;
    int c  = threadIdx.x;
    int xy = d_selxy[bp];
    float fx = (float)(xy & 0xFFFF) * 0.25f;
    float fy = (float)(xy >> 16)    * 0.25f;
    int x0 = (int)floorf(fx);
    int y0 = (int)floorf(fy);
    float wx = fx - (float)x0, wy = fy - (float)y0;
    int gx0 = x0 - 3, gy0 = y0 - 3;

    const float* base = d_cl + (size_t)b * OH * OW * CH + c;

    float v[64];
    #pragma unroll
    for (int pt = 0; pt < 64; pt++) {
        int yy = pt >> 3, xx = pt & 7;
        int gy = gy0 + yy, gx = gx0 + xx;
        bool ok = (gx >= 0) & (gx < OW) & (gy >= 0) & (gy < OH);
        v[pt] = ok ? __ldg(base + ((size_t)gy * OW + gx) * CH) : 0.f;
    }

    float w00 = (1.f - wx) * (1.f - wy);
    float w10 = wx * (1.f - wy);
    float w01 = (1.f - wx) * wy;
    float w11 = wx * wy;

    #pragma unroll
    for (int j = 0; j < 7; j++) {
        #pragma unroll
        for (int i = 0; i < 7; i++) {
            float acc = v[j*8 + i]       * w00
                      + v[j*8 + i + 1]   * w10
                      + v[(j+1)*8 + i]   * w01
                      + v[(j+1)*8 + i+1] * w11;
            s[c * 49 + (j*7 + i)] = acc;
        }
    }
    __syncthreads();

    float* o = out + (size_t)bp * (CH * 49);
    for (int k = threadIdx.x; k < CH * 49; k += 128)
        o[k] = s[k];
}

// ================= K5: patches_c — on-the-fly imap conv =================
__global__ void k_patches_c(
    const float* __restrict__ frame,
    const float* __restrict__ wc,
    const float* __restrict__ bc,
    float* __restrict__ out)
{
    __shared__ float s_in[121];
    int bp = blockIdx.x;
    int b  = bp / NP;
    int c  = threadIdx.x;
    int xy = d_selxy[bp];
    float fx = (float)(xy & 0xFFFF) * 0.25f;
    float fy = (float)(xy >> 16)    * 0.25f;
    int x0 = (int)floorf(fx);
    int y0 = (int)floorf(fy);
    float wx = fx - (float)x0, wy = fy - (float)y0;

    const float* f = frame + (size_t)b * H * W;
    int row0 = y0 * 4 - 3, col0 = x0 * 4 - 3;
    for (int i = threadIdx.x; i < 121; i += 128) {
        int r = i / 11, cc = i - r * 11;
        int yyy = row0 + r, xxx = col0 + cc;
        s_in[i] = (yyy >= 0 && yyy < H && xxx >= 0 && xxx < W) ? f[yyy*W + xxx] : 0.f;
    }
    float wreg[49];
    #pragma unroll
    for (int i = 0; i < 49; i++) wreg[i] = __ldg(wc + c*49 + i);
    float bias = __ldg(bc + c);
    __syncthreads();

    float wts[4] = { (1.f-wx)*(1.f-wy), wx*(1.f-wy), (1.f-wx)*wy, wx*wy };
    float acc = 0.f;
    #pragma unroll
    for (int n = 0; n < 4; n++) {
        int dxn = n & 1, dyn = n >> 1;
        int xi = x0 + dxn, yi = y0 + dyn;
        if (xi < OW && yi < OH) {
            float v = bias;
            #pragma unroll
            for (int ky = 0; ky < 7; ky++)
                #pragma unroll
                for (int kx = 0; kx < 7; kx++)
                    v = fmaf(s_in[(dyn*4 + ky)*11 + (dxn*4 + kx)], wreg[ky*7 + kx], v);
            v = fmaxf(v, 0.f);
            acc += v * wts[n];
        }
    }
    out[(size_t)bp * CH + c] = acc;
}

// ---------------- launch: fork-join across two streams ---------------------------
extern "C" void kernel_launch(void* const* d_in, const int* in_sizes, int n_in,
                              void* d_out, int out_size) {
    const float* frame = (const float*)d_in[0];
    const float* w_f   = (const float*)d_in[1];
    const float* b_f   = (const float*)d_in[2];
    const float* w_c   = (const float*)d_in[3];
    const float* b_c   = (const float*)d_in[4];

    float* out        = (float*)d_out;
    float* out_coords = out;                                   // 8*192*2
    float* out_pf     = out + 3072;                            // 8*192*128*49
    float* out_pc     = out + 3072 + 9633792;                  // 8*192*128
    float* out_fmap   = out + 3072 + 9633792 + 196608;         // 8*128*120*160

    static cudaStream_t s1 = 0;
    static cudaEvent_t e_fork = 0, e_topk = 0, e_side = 0;
    if (!s1) {
        cudaStreamCreateWithFlags(&s1, cudaStreamNonBlocking);
        cudaEventCreateWithFlags(&e_fork, cudaEventDisableTiming);
        cudaEventCreateWithFlags(&e_topk, cudaEventDisableTiming);
        cudaEventCreateWithFlags(&e_side, cudaEventDisableTiming);
    }

    // fork
    cudaEventRecord(e_fork, 0);
    cudaStreamWaitEvent(s1, e_fork, 0);

    // side stream: harris -> topk -> patches_c
    k_harris<<<BN*256, 256, 0, s1>>>(frame);
    k_topk  <<<BN, 256, 0, s1>>>(out_coords);
    cudaEventRecord(e_topk, s1);
    k_patches_c<<<BN*NP, 128, 0, s1>>>(frame, w_c, b_c, out_pc);
    cudaEventRecord(e_side, s1);

    // main stream: wprep -> conv -> patches_f (needs conv output AND topk coords)
    k_wprep<<<25, 128>>>(w_f, b_f);
    dim3 gconv(OW/16, OH/2, BN);
    k_conv<<<gconv, 128>>>(frame, out_fmap);
    cudaStreamWaitEvent(0, e_topk, 0);
    k_patches_f<<<BN*NP, 128>>>(out_pf);

    // join
    cudaStreamWaitEvent(0, e_side, 0);
}

// round 7
// speedup vs baseline: 1.3386x; 1.1693x over previous
#include <cuda_runtime.h>
#include <math.h>
#include <float.h>

#define BN 8
#define H 480
#define W 640
#define OH 120
#define OW 160
#define CH 128
#define NP 192

typedef unsigned long long u64;

// ---------------- scratch ----------------
__device__ float d_cellval[BN*256];
__device__ int   d_cellxy[BN*256];
__device__ int   d_selxy[BN*NP];
// channel-last fmap copy: [b][oy][ox][ch]
__device__ float d_cl[(size_t)BN*OH*OW*CH];
// pre-paired weights/bias for conv: [tap][pair] and [pair]
__device__ u64 d_wpair[49*64];
__device__ u64 d_bpair[64];

// ---------------- f32x2 helpers ----------------
__device__ __forceinline__ u64 pack2(float lo, float hi) {
    u64 r; asm("mov.b64 %0, {%1, %2};" : "=l"(r) : "f"(lo), "f"(hi)); return r;
}
__device__ __forceinline__ void unpack2(u64 v, float& lo, float& hi) {
    asm("mov.b64 {%0, %1}, %2;" : "=f"(lo), "=f"(hi) : "l"(v));
}
__device__ __forceinline__ u64 ffma2(u64 a, u64 b, u64 c) {
    u64 d; asm("fma.rn.f32x2 %0, %1, %2, %3;" : "=l"(d) : "l"(a), "l"(b), "l"(c)); return d;
}

// ================= K0: weight prep (one-time transpose into pairs) =============
__global__ void k_wprep(const float* __restrict__ wf, const float* __restrict__ bf) {
    int i = blockIdx.x * blockDim.x + threadIdx.x;
    if (i < 49*64) {
        int t = i >> 6, p = i & 63;
        d_wpair[i] = pack2(__ldg(wf + (2*p)*49 + t), __ldg(wf + (2*p+1)*49 + t));
    }
    if (i < 64) d_bpair[i] = pack2(__ldg(bf + 2*i), __ldg(bf + 2*i + 1));
}

// ================= K1: fused harris + per-cell argmax (v2: fold products) =======
__global__ __launch_bounds__(256) void k_harris(const float* __restrict__ frame) {
    __shared__ float sf[37][48];
    __shared__ float shxx[36][40], shyy[36][40], shxy[36][40];
    __shared__ float sv[256];
    __shared__ int   si[256];

    int blk = blockIdx.x;
    int b = blk >> 8, cell = blk & 255;
    int gh = cell >> 4, gw = cell & 15;
    int gx0 = gw * 40, gy0 = gh * 30;
    int X0 = gx0 - 3, Y0 = gy0 - 3;
    const float* f = frame + (size_t)b * H * W;
    int tid = threadIdx.x;

    for (int i = tid; i < 37 * 47; i += 256) {
        int r = i / 47, c = i - r * 47;
        int x = X0 + c, y = Y0 + r;
        sf[r][c] = (x >= 0 && x < W && y >= 0 && y < H) ? f[y * W + x] : 0.f;
    }
    __syncthreads();

    // horizontal 7-tap sums of gradient products, products computed on the fly
    for (int i = tid; i < 36 * 40; i += 256) {
        int r = i / 40, c = i - r * 40;
        int y = Y0 + r;
        float a = 0.f, bb = 0.f, cc2 = 0.f;
        if (y >= 0 && y < H) {
            bool ylast = (y == H - 1);
            #pragma unroll
            for (int k = 0; k < 7; k++) {
                int cw = c + k;
                int x = X0 + cw;
                if (x >= 0 && x < W) {
                    float dx = (x < W - 1) ? (sf[r][cw+1] - sf[r][cw])
                                           : (sf[r][cw-1] - sf[r][cw-2]);
                    float dy = !ylast ? (sf[r+1][cw] - sf[r][cw])
                                      : (sf[r-1][cw] - sf[r-2][cw]);
                    a   = fmaf(dx, dx, a);
                    bb  = fmaf(dy, dy, bb);
                    cc2 = fmaf(dx, dy, cc2);
                }
            }
        }
        shxx[r][c] = a; shyy[r][c] = bb; shxy[r][c] = cc2;
    }
    __syncthreads();

    float bv = -FLT_MAX;
    int   bi = 0x7FFFFFFF;
    for (int fi = tid; fi < 1200; fi += 256) {
        int py = fi / 40, px = fi - py * 40;
        float a = 0.f, bb = 0.f, cc = 0.f;
        #pragma unroll
        for (int k = 0; k < 7; k++) {
            a  += shxx[py + k][px];
            bb += shyy[py + k][px];
            cc += shxy[py + k][px];
        }
        float Ixx = a / 49.0f, Iyy = bb / 49.0f, Ixy = cc / 49.0f;
        float g = (Ixx * Iyy - Ixy * Ixy) / (Ixx + Iyy + 1e-8f);
        if (g > bv) { bv = g; bi = fi; }
    }
    sv[tid] = bv; si[tid] = bi;
    __syncthreads();
    for (int s = 128; s > 0; s >>= 1) {
        if (tid < s) {
            float v2 = sv[tid + s]; int i2 = si[tid + s];
            if (v2 > sv[tid] || (v2 == sv[tid] && i2 < si[tid])) { sv[tid] = v2; si[tid] = i2; }
        }
        __syncthreads();
    }
    if (tid == 0) {
        int fi = si[0];
        int py = fi / 40, px = fi - py * 40;
        d_cellval[blk] = sv[0];
        d_cellxy[blk]  = ((gy0 + py) << 16) | (gx0 + px);
    }
}

// ================= K2: top-192 by rank count (stable) =================
__global__ void k_topk(float* __restrict__ out_coords) {
    __shared__ float sv[256];
    __shared__ int   sxy[256];
    int b = blockIdx.x, i = threadIdx.x;
    sv[i]  = d_cellval[b*256 + i];
    sxy[i] = d_cellxy[b*256 + i];
    __syncthreads();
    float v = sv[i];
    int rank = 0;
    #pragma unroll 8
    for (int j = 0; j < 256; j++) {
        float vj = sv[j];
        rank += (vj > v) || (vj == v && j < i);
    }
    if (rank < NP) {
        int xy = sxy[i];
        int x = xy & 0xFFFF, y = xy >> 16;
        out_coords[((size_t)b*NP + rank)*2 + 0] = (float)x;
        out_coords[((size_t)b*NP + rank)*2 + 1] = (float)y;
        d_selxy[b*NP + rank] = xy;
    }
}

// ================= K3: conv v7 — conflict-free epilogue =================
// Block 128 thr = 4 warps; warp -> (oyr = w>>1, pxh = w&1). Lane owns 2 channel
// pairs (cA=2*lane, cB=64+2*lane) x 8 px of one output row.
#define SO_STRIDE 130   // px-major staging stride (mod 32 == 2 -> conflict-free)

__global__ __launch_bounds__(128, 6) void k_conv(
    const float* __restrict__ frame,
    float* __restrict__ fmap)
{
    __shared__ __align__(16) u64 s_w[49*64];    // 25088 B; overlaid by s_out later
    __shared__ __align__(16) u64 s_in[11*68];   // 5984 B
    float* s_out = (float*)s_w;                 // overlay: [oyr][px16][ch] stride 130

    int tid  = threadIdx.x;
    int lane = tid & 31;
    int warp = tid >> 5;
    int oyr  = warp >> 1;
    int pxh  = warp & 1;

    int ox0 = blockIdx.x * 16;
    int oy0 = blockIdx.y * 2;
    int b   = blockIdx.z;
    const float* f = frame + (size_t)b * H * W;
    int row0 = oy0 * 4 - 3, col0 = ox0 * 4 - 3;

    for (int i = tid; i < 49*64; i += 128) s_w[i] = d_wpair[i];
    for (int i = tid; i < 11*67; i += 128) {
        int r = i / 67, c = i - r * 67;
        int y = row0 + r, x = col0 + c;
        float v = (y >= 0 && y < H && x >= 0 && x < W) ? f[(size_t)y*W + x] : 0.f;
        s_in[r * 68 + c] = pack2(v, v);
    }
    u64 biasA = d_bpair[lane];
    u64 biasB = d_bpair[32 + lane];
    __syncthreads();

    u64 accA[8], accB[8];
    #pragma unroll
    for (int i = 0; i < 8; i++) { accA[i] = biasA; accB[i] = biasB; }

    #pragma unroll
    for (int ky = 0; ky < 7; ky++) {
        int row = oyr * 4 + ky;
        u64 wkA[7], wkB[7];
        #pragma unroll
        for (int kx = 0; kx < 7; kx++) {
            wkA[kx] = s_w[(ky*7 + kx) * 64 + lane];
            wkB[kx] = s_w[(ky*7 + kx) * 64 + 32 + lane];
        }
        const u64* inp = s_in + row * 68 + pxh * 32;
        #pragma unroll
        for (int c = 0; c < 35; c++) {
            u64 v = inp[c];
            if (c < 32) {
                int px = c >> 2, kx = c & 3;
                accA[px] = ffma2(v, wkA[kx], accA[px]);
                accB[px] = ffma2(v, wkB[kx], accB[px]);
            }
            if (c >= 4 && (c & 3) < 3) {
                int px = (c - 4) >> 2, kx = 4 + (c & 3);
                accA[px] = ffma2(v, wkA[kx], accA[px]);
                accB[px] = ffma2(v, wkB[kx], accB[px]);
            }
        }
    }

    // relu + channel-last store (coalesced 256B segments per warp per px)
    int oy = oy0 + oyr;
    float loA[8], hiA[8], loB[8], hiB[8];
    #pragma unroll
    for (int px = 0; px < 8; px++) {
        float a0, a1;
        unpack2(accA[px], a0, a1); loA[px] = fmaxf(a0, 0.f); hiA[px] = fmaxf(a1, 0.f);
        unpack2(accB[px], a0, a1); loB[px] = fmaxf(a0, 0.f); hiB[px] = fmaxf(a1, 0.f);
        int ox = ox0 + pxh * 8 + px;
        u64* clp = (u64*)(d_cl + (((size_t)(b*OH + oy))*OW + ox) * CH);
        clp[lane]      = pack2(loA[px], hiA[px]);
        clp[32 + lane] = pack2(loB[px], hiB[px]);
    }

    // stage required layout into smem, px-major (conflict-free u64 writes)
    __syncthreads();
    #pragma unroll
    for (int px = 0; px < 8; px++) {
        int pxg = pxh * 8 + px;
        u64* po = (u64*)(s_out + (oyr*16 + pxg) * SO_STRIDE);
        po[lane]      = pack2(loA[px], hiA[px]);
        po[32 + lane] = pack2(loB[px], hiB[px]);
    }
    __syncthreads();

    // coalesced copy-out (reads stride-130: conflict-free)
    for (int i = tid; i < 2 * 128 * 16; i += 128) {
        int px = i & 15;
        int ch = (i >> 4) & 127;
        int r  = i >> 11;
        fmap[(((size_t)(b*CH + ch)) * OH + (oy0 + r)) * OW + ox0 + px] =
            s_out[(r*16 + px) * SO_STRIDE + ch];
    }
}

// ================= K4: patches_f — channel-last coalesced gather =============
__global__ __launch_bounds__(128) void k_patches_f(float* __restrict__ out) {
    __shared__ float s[CH * 49];
    int bp = blockIdx.x;
    int b  = bp / NP;
    int c  = threadIdx.x;
    int xy = d_selxy[bp];
    float fx = (float)(xy & 0xFFFF) * 0.25f;
    float fy = (float)(xy >> 16)    * 0.25f;
    int x0 = (int)floorf(fx);
    int y0 = (int)floorf(fy);
    float wx = fx - (float)x0, wy = fy - (float)y0;
    int gx0 = x0 - 3, gy0 = y0 - 3;

    const float* base = d_cl + (size_t)b * OH * OW * CH + c;

    float v[64];
    #pragma unroll
    for (int pt = 0; pt < 64; pt++) {
        int yy = pt >> 3, xx = pt & 7;
        int gy = gy0 + yy, gx = gx0 + xx;
        bool ok = (gx >= 0) & (gx < OW) & (gy >= 0) & (gy < OH);
        v[pt] = ok ? __ldg(base + ((size_t)gy * OW + gx) * CH) : 0.f;
    }

    float w00 = (1.f - wx) * (1.f - wy);
    float w10 = wx * (1.f - wy);
    float w01 = (1.f - wx) * wy;
    float w11 = wx * wy;

    #pragma unroll
    for (int j = 0; j < 7; j++) {
        #pragma unroll
        for (int i = 0; i < 7; i++) {
            float acc = v[j*8 + i]       * w00
                      + v[j*8 + i + 1]   * w10
                      + v[(j+1)*8 + i]   * w01
                      + v[(j+1)*8 + i+1] * w11;
            s[c * 49 + (j*7 + i)] = acc;
        }
    }
    __syncthreads();

    float* o = out + (size_t)bp * (CH * 49);
    for (int k = threadIdx.x; k < CH * 49; k += 128)
        o[k] = s[k];
}

// ================= K5: patches_c v2 — smem-staged weights =================
__global__ __launch_bounds__(128) void k_patches_c(
    const float* __restrict__ frame,
    const float* __restrict__ wc,
    const float* __restrict__ bc,
    float* __restrict__ out)
{
    __shared__ float s_w[CH * 49];       // 25KB, coalesced-staged
    __shared__ float s_in[121];
    int bp = blockIdx.x;
    int b  = bp / NP;
    int c  = threadIdx.x;
    int xy = d_selxy[bp];
    float fx = (float)(xy & 0xFFFF) * 0.25f;
    float fy = (float)(xy >> 16)    * 0.25f;
    int x0 = (int)floorf(fx);
    int y0 = (int)floorf(fy);
    float wx = fx - (float)x0, wy = fy - (float)y0;

    const float* f = frame + (size_t)b * H * W;
    int row0 = y0 * 4 - 3, col0 = x0 * 4 - 3;
    for (int i = threadIdx.x; i < CH * 49; i += 128) s_w[i] = __ldg(wc + i);
    for (int i = threadIdx.x; i < 121; i += 128) {
        int r = i / 11, cc = i - r * 11;
        int yyy = row0 + r, xxx = col0 + cc;
        s_in[i] = (yyy >= 0 && yyy < H && xxx >= 0 && xxx < W) ? f[yyy*W + xxx] : 0.f;
    }
    float bias = __ldg(bc + c);
    __syncthreads();

    float wreg[49];
    #pragma unroll
    for (int i = 0; i < 49; i++) wreg[i] = s_w[c*49 + i];   // stride 49 (odd): conflict-free

    float wts[4] = { (1.f-wx)*(1.f-wy), wx*(1.f-wy), (1.f-wx)*wy, wx*wy };
    float acc = 0.f;
    #pragma unroll
    for (int n = 0; n < 4; n++) {
        int dxn = n & 1, dyn = n >> 1;
        int xi = x0 + dxn, yi = y0 + dyn;
        if (xi < OW && yi < OH) {
            float v = bias;
            #pragma unroll
            for (int ky = 0; ky < 7; ky++)
                #pragma unroll
                for (int kx = 0; kx < 7; kx++)
                    v = fmaf(s_in[(dyn*4 + ky)*11 + (dxn*4 + kx)], wreg[ky*7 + kx], v);
            v = fmaxf(v, 0.f);
            acc += v * wts[n];
        }
    }
    out[(size_t)bp * CH + c] = acc;
}

// ---------------- launch: fork-join across two streams ---------------------------
extern "C" void kernel_launch(void* const* d_in, const int* in_sizes, int n_in,
                              void* d_out, int out_size) {
    const float* frame = (const float*)d_in[0];
    const float* w_f   = (const float*)d_in[1];
    const float* b_f   = (const float*)d_in[2];
    const float* w_c   = (const float*)d_in[3];
    const float* b_c   = (const float*)d_in[4];

    float* out        = (float*)d_out;
    float* out_coords = out;                                   // 8*192*2
    float* out_pf     = out + 3072;                            // 8*192*128*49
    float* out_pc     = out + 3072 + 9633792;                  // 8*192*128
    float* out_fmap   = out + 3072 + 9633792 + 196608;         // 8*128*120*160

    static cudaStream_t s1 = 0;
    static cudaEvent_t e_fork = 0, e_topk = 0, e_side = 0;
    if (!s1) {
        cudaStreamCreateWithFlags(&s1, cudaStreamNonBlocking);
        cudaEventCreateWithFlags(&e_fork, cudaEventDisableTiming);
        cudaEventCreateWithFlags(&e_topk, cudaEventDisableTiming);
        cudaEventCreateWithFlags(&e_side, cudaEventDisableTiming);
    }

    // fork
    cudaEventRecord(e_fork, 0);
    cudaStreamWaitEvent(s1, e_fork, 0);

    // side stream: harris -> topk -> patches_c
    k_harris<<<BN*256, 256, 0, s1>>>(frame);
    k_topk  <<<BN, 256, 0, s1>>>(out_coords);
    cudaEventRecord(e_topk, s1);
    k_patches_c<<<BN*NP, 128, 0, s1>>>(frame, w_c, b_c, out_pc);
    cudaEventRecord(e_side, s1);

    // main stream: wprep -> conv -> patches_f (needs conv output AND topk coords)
    k_wprep<<<25, 128>>>(w_f, b_f);
    dim3 gconv(OW/16, OH/2, BN);
    k_conv<<<gconv, 128>>>(frame, out_fmap);
    cudaStreamWaitEvent(0, e_topk, 0);
    k_patches_f<<<BN*NP, 128>>>(out_pf);

    // join
    cudaStreamWaitEvent(0, e_side, 0);
}